// round 11
// baseline (speedup 1.0000x reference)
#include <cuda_runtime.h>
#include <math.h>

typedef unsigned long long u64;

static constexpr int Bc   = 8;
static constexpr int NQ   = 512;
static constexpr int NKV  = 512;
static constexpr int Hc   = 16;
static constexpr int Dc   = 256;

// scratch (allocation-free rule: device globals)
__device__ float g_proj[Bc * NKV * Dc];   // 4 MB
__device__ float g_attn[Bc * NQ  * Dc];   // 4 MB

// ---------- packed f32x2 helpers ----------
__device__ __forceinline__ u64 pack2(float x, float y) {
    u64 d; asm("mov.b64 %0, {%1, %2};" : "=l"(d) : "f"(x), "f"(y)); return d;
}
__device__ __forceinline__ void unpack2(u64 v, float& x, float& y) {
    asm("mov.b64 {%0, %1}, %2;" : "=f"(x), "=f"(y) : "l"(v));
}
__device__ __forceinline__ u64 fma2(u64 a, u64 b, u64 c) {
    u64 d; asm("fma.rn.f32x2 %0, %1, %2, %3;" : "=l"(d) : "l"(a), "l"(b), "l"(c)); return d;
}
__device__ __forceinline__ float ex2f(float x) {
    float r; asm("ex2.approx.f32 %0, %1;" : "=f"(r) : "f"(x)); return r;
}

__device__ __forceinline__ void cp_async16(void* smem, const void* gptr) {
    unsigned saddr = (unsigned)__cvta_generic_to_shared(smem);
    asm volatile("cp.async.cg.shared.global [%0], [%1], 16;" :: "r"(saddr), "l"(gptr));
}
#define CP_COMMIT()  asm volatile("cp.async.commit_group;" ::: "memory")
#define CP_WAIT(N)   asm volatile("cp.async.wait_group %0;" :: "n"(N) : "memory")

__device__ __forceinline__ void barx128(int id) {
    asm volatile("bar.sync %0, 128;" :: "r"(id) : "memory");
}

// ============================================================
// GEMM: C[m,n] = sum_k A[m,k] * W[n,k] + bias[n]
// BM=128, BN=64, BK=16, *512* threads (16 warps/SM -> 4 per SMSP).
// Each thread: 4m (2 f32x2 pairs) x 4n. Double-buffered smem,
// one sync per tile, LDG two tiles ahead.
// ============================================================
__global__ __launch_bounds__(512)
void gemm_bias_kernel(const float* __restrict__ A, const float* __restrict__ W,
                      const float* __restrict__ bias, float* __restrict__ C,
                      int M, int N, int K)
{
    __shared__ float As[2][16][132];   // [buf][k][m]
    __shared__ float Bs[2][16][68];    // [buf][k][n]

    const int t  = threadIdx.x;
    const int tx = t & 15;             // n: 4 outputs at tx*4
    const int ty = t >> 4;             // m: 4 rows at ty*4 (2 pairs)
    const int m0 = blockIdx.y * 128;
    const int n0 = blockIdx.x * 64;

    const int rA = t >> 2;             // 0..127
    const int pA = (t & 3) * 4;        // k base 0,4,8,12
    const bool wact = (t < 256);
    const int rW = (t >> 2) & 63;      // 0..63
    const int pW = (t & 3) * 4;

    u64 acc[2][4];
#pragma unroll
    for (int i = 0; i < 2; i++)
#pragma unroll
        for (int j = 0; j < 4; j++) acc[i][j] = pack2(0.f, 0.f);

    const float* aptr = A + (size_t)(m0 + rA) * K + pA;
    const float* wptr = W + (size_t)(n0 + rW) * K + pW;

    float4 a0 = *reinterpret_cast<const float4*>(aptr);
    float4 w0 = wact ? *reinterpret_cast<const float4*>(wptr) : make_float4(0,0,0,0);

    // store tile 0 into buf 0
    As[0][pA + 0][rA] = a0.x; As[0][pA + 1][rA] = a0.y;
    As[0][pA + 2][rA] = a0.z; As[0][pA + 3][rA] = a0.w;
    if (wact) {
        Bs[0][pW + 0][rW] = w0.x; Bs[0][pW + 1][rW] = w0.y;
        Bs[0][pW + 2][rW] = w0.z; Bs[0][pW + 3][rW] = w0.w;
    }
    a0 = *reinterpret_cast<const float4*>(aptr + 16);
    if (wact) w0 = *reinterpret_cast<const float4*>(wptr + 16);
    __syncthreads();

    const int NT = K / 16;   // 16
    for (int i = 0; i < NT; i++) {
        const int buf = i & 1;
        if (i < NT - 1) {
            As[buf ^ 1][pA + 0][rA] = a0.x; As[buf ^ 1][pA + 1][rA] = a0.y;
            As[buf ^ 1][pA + 2][rA] = a0.z; As[buf ^ 1][pA + 3][rA] = a0.w;
            if (wact) {
                Bs[buf ^ 1][pW + 0][rW] = w0.x; Bs[buf ^ 1][pW + 1][rW] = w0.y;
                Bs[buf ^ 1][pW + 2][rW] = w0.z; Bs[buf ^ 1][pW + 3][rW] = w0.w;
            }
        }
        if (i < NT - 2) {
            a0 = *reinterpret_cast<const float4*>(aptr + (i + 2) * 16);
            if (wact) w0 = *reinterpret_cast<const float4*>(wptr + (i + 2) * 16);
        }
#pragma unroll
        for (int kk = 0; kk < 16; kk++) {
            float4 av = *reinterpret_cast<const float4*>(&As[buf][kk][ty * 4]);
            u64 am0 = pack2(av.x, av.y);
            u64 am1 = pack2(av.z, av.w);
            float4 bv = *reinterpret_cast<const float4*>(&Bs[buf][kk][tx * 4]);
            u64 bd[4] = {pack2(bv.x, bv.x), pack2(bv.y, bv.y),
                         pack2(bv.z, bv.z), pack2(bv.w, bv.w)};
#pragma unroll
            for (int j = 0; j < 4; j++) {
                acc[0][j] = fma2(am0, bd[j], acc[0][j]);
                acc[1][j] = fma2(am1, bd[j], acc[1][j]);
            }
        }
        __syncthreads();
    }

    float4 bv = *reinterpret_cast<const float4*>(bias + n0 + tx * 4);
#pragma unroll
    for (int i = 0; i < 2; i++) {
        float lo[4], hi[4];
#pragma unroll
        for (int j = 0; j < 4; j++) unpack2(acc[i][j], lo[j], hi[j]);
        float4 o0 = make_float4(lo[0] + bv.x, lo[1] + bv.y, lo[2] + bv.z, lo[3] + bv.w);
        float4 o1 = make_float4(hi[0] + bv.x, hi[1] + bv.y, hi[2] + bv.z, hi[3] + bv.w);
        *reinterpret_cast<float4*>(C + (size_t)(m0 + ty * 4 + 2 * i) * N + n0 + tx * 4) = o0;
        *reinterpret_cast<float4*>(C + (size_t)(m0 + ty * 4 + 2 * i + 1) * N + n0 + tx * 4) = o1;
    }
}

// ============================================================
// Fused masked softmax + per-head aggregation + L2-norm rescale.
// 512 threads = 4 k-split quarters x (8 qgroups x 16 heads), qpt=4.
// Features/messages/adjacency staged via cp.async into double-buffered
// dynamic smem. One named barrier per chunk; mask+exp fused in log2
// domain; feature fetch via LDS.128.
// ============================================================
static constexpr int KC = 8;
static constexpr int FEAT_F = 4 * 2 * KC * Dc;        // 16384 floats
static constexpr int MSG_F  = 4 * 2 * 32 * 132;       // 33792 floats
static constexpr int ADJ_I  = 4 * 2 * 32 * 8;         // 2048 ints
static constexpr int SMEM_ATTN = (FEAT_F + MSG_F + ADJ_I) * 4;   // 208896 B

__global__ __launch_bounds__(512)
void attn_kernel(const float* __restrict__ messages, const int* __restrict__ adj,
                 float* __restrict__ outp)
{
    extern __shared__ __align__(16) float smemF[];
    float* featS = smemF;                  // [4][2][KC*256]
    float* msgS  = smemF + FEAT_F;         // [4][2][32][132]
    int*   adjS  = (int*)(smemF + FEAT_F + MSG_F);   // [4][2][32][8]

    const int t  = threadIdx.x;
    const int quarter = t >> 7;
    const int lt = t & 127;
    const int h  = lt & 15;
    const int qg = lt >> 4;                // 0..7
    const int b  = blockIdx.y;
    const int qb0 = blockIdx.x * 32;
    const int qbase = qb0 + qg * 4;

    const float4* msgG  = (const float4*)(messages + (size_t)(b * NQ + qb0) * NKV * Hc);
    const int*    adjG  = adj + (size_t)(b * NQ + qb0) * NKV;
    const float4* proj4 = (const float4*)(g_proj + (size_t)b * NKV * Dc);

    float l[4]  = {0.f, 0.f, 0.f, 0.f};
    float s2[4] = {0.f, 0.f, 0.f, 0.f};
    u64 acc[4][8];
#pragma unroll
    for (int qi = 0; qi < 4; qi++)
#pragma unroll
        for (int j = 0; j < 8; j++) acc[qi][j] = pack2(0.f, 0.f);

    auto load_chunk = [&](int c, int buf) {
        const int k0 = c * KC;
        // features: 512 f4, swizzled (granule (kk, hh*4+j) -> j*128+kk*16+(hh^2j))
        float* fb = featS + (quarter * 2 + buf) * (KC * Dc);
#pragma unroll
        for (int i = 0; i < 4; i++) {
            int lin = lt + i * 128;
            int kk = lin >> 6, g = lin & 63;
            int hh = g >> 2, j = g & 3;
            int dstf4 = j * (KC * 16) + kk * 16 + (hh ^ (2 * j));
            cp_async16(fb + dstf4 * 4, &proj4[(size_t)(k0 + kk) * 64 + g]);
        }
        // messages: 1024 f4 granules -> msgS[q][g32*4..]
        float* mb = msgS + ((quarter * 2 + buf) * 32) * 132;
#pragma unroll
        for (int i = 0; i < 8; i++) {
            int lin = lt + i * 128;
            int q = lin >> 5, g32 = lin & 31;
            cp_async16(mb + q * 132 + g32 * 4,
                       &msgG[((size_t)q * NKV + k0 + (g32 >> 2)) * 4 + (g32 & 3)]);
        }
        // adjacency: 64 granules (32 q x 8 k)
        if (lt < 64) {
            int q = lt >> 1, hf = lt & 1;
            cp_async16(adjS + ((quarter * 2 + buf) * 32 + q) * 8 + hf * 4,
                       adjG + (size_t)q * NKV + k0 + hf * 4);
        }
        CP_COMMIT();
    };

    const float L2E = 1.4426950408889634f;
    const int NCI = NKV / KC / 4;   // 16 chunks per quarter
    load_chunk(quarter, 0);

    for (int ci = 0; ci < NCI; ci++) {
        const int buf = ci & 1;
        CP_WAIT(0);                 // chunk ci's data has landed
        barx128(quarter + 1);       // everyone done reading buf^1, sees new buf
        if (ci + 1 < NCI) load_chunk(4 * (ci + 1) + quarter, buf ^ 1);

        const float* fb = featS + (quarter * 2 + buf) * (KC * Dc);
        const float* mb = msgS + ((quarter * 2 + buf) * 32) * 132;
        const int*   ab = adjS + ((quarter * 2 + buf) * 32) * 8;

#pragma unroll
        for (int g = 0; g < 2; g++) {
            int4 av[4];
#pragma unroll
            for (int qi = 0; qi < 4; qi++)
                av[qi] = *reinterpret_cast<const int4*>(&ab[(qg * 4 + qi) * 8 + g * 4]);
#pragma unroll
            for (int u = 0; u < 4; u++) {
                const int kk = g * 4 + u;
                // feature row for this head: 4x LDS.128
                u64 f[8];
#pragma unroll
                for (int j = 0; j < 4; j++) {
                    float4 fv = *reinterpret_cast<const float4*>(
                        &fb[(j * (KC * 16) + kk * 16 + (h ^ (2 * j))) * 4]);
                    f[2 * j]     = pack2(fv.x, fv.y);
                    f[2 * j + 1] = pack2(fv.z, fv.w);
                }
#pragma unroll
                for (int qi = 0; qi < 4; qi++) {
                    float mv = mb[(qg * 4 + qi) * 132 + kk * 16 + h];
                    int a = (&av[qi].x)[u];
                    float lg = fmaf(mv, L2E, (a > 0) ? 0.f : -2e9f);
                    float p = ex2f(lg);
                    l[qi] += p;
                    s2[qi] = fmaf(p, p, s2[qi]);
                    u64 pp = pack2(p, p);
#pragma unroll
                    for (int j = 0; j < 8; j++)
                        acc[qi][j] = fma2(pp, f[j], acc[qi][j]);
                }
            }
        }
    }

    // ---- combine quarters (overlay redS on msgS region) ----
    __syncthreads();
    float* redS = msgS;    // 3 * 128 * 73 floats <= MSG_F
    if (quarter > 0) {
        float* s = redS + ((size_t)(quarter - 1) * 128 + lt) * 73;
#pragma unroll
        for (int qi = 0; qi < 4; qi++) {
#pragma unroll
            for (int j = 0; j < 8; j++)
                unpack2(acc[qi][j], s[qi * 18 + 2 * j], s[qi * 18 + 2 * j + 1]);
            s[qi * 18 + 16] = l[qi];
            s[qi * 18 + 17] = s2[qi];
        }
    }
    __syncthreads();
    if (quarter == 0) {
#pragma unroll
        for (int qi = 0; qi < 4; qi++) {
            float v[16];
#pragma unroll
            for (int j = 0; j < 8; j++) unpack2(acc[qi][j], v[2 * j], v[2 * j + 1]);
            float lsum = l[qi], s2sum = s2[qi];
#pragma unroll
            for (int r = 0; r < 3; r++) {
                const float* s = redS + ((size_t)r * 128 + lt) * 73 + qi * 18;
#pragma unroll
                for (int j = 0; j < 16; j++) v[j] += s[j];
                lsum  += s[16];
                s2sum += s[17];
            }
            float w = sqrtf(s2sum) / (lsum * lsum);
            float* o = outp + (size_t)(b * NQ + qbase + qi) * Dc + h * 16;
#pragma unroll
            for (int j = 0; j < 4; j++) {
                float4 ov = make_float4(v[4*j] * w, v[4*j+1] * w, v[4*j+2] * w, v[4*j+3] * w);
                *reinterpret_cast<float4*>(o + 4 * j) = ov;
            }
        }
    }
}

// ============================================================
extern "C" void kernel_launch(void* const* d_in, const int* in_sizes, int n_in,
                              void* d_out, int out_size)
{
    const float* v_inv    = (const float*)d_in[0];
    const float* messages = (const float*)d_in[1];
    const int*   adjm     = (const int*)d_in[2];
    const float* W_in     = (const float*)d_in[3];
    const float* b_in     = (const float*)d_in[4];
    const float* W_out    = (const float*)d_in[5];
    const float* b_out    = (const float*)d_in[6];
    float* out = (float*)d_out;

    float *p_proj = nullptr, *p_attn = nullptr;
    cudaGetSymbolAddress((void**)&p_proj, g_proj);
    cudaGetSymbolAddress((void**)&p_attn, g_attn);

    cudaFuncSetAttribute(attn_kernel, cudaFuncAttributeMaxDynamicSharedMemorySize, SMEM_ATTN);

    // 1) proj = v_inv @ W_in^T + b_in      [4096 x 256]
    {
        dim3 grid(Dc / 64, (Bc * NKV) / 128);
        gemm_bias_kernel<<<grid, 512>>>(v_inv, W_in, b_in, p_proj, Bc * NKV, Dc, Dc);
    }
    // 2) fused attention -> g_attn         [4096 x 256]
    {
        dim3 grid(NQ / 32, Bc);
        attn_kernel<<<grid, 512, SMEM_ATTN>>>(messages, adjm, p_attn);
    }
    // 3) out = g_attn @ W_out^T + b_out
    {
        dim3 grid(Dc / 64, (Bc * NQ) / 128);
        gemm_bias_kernel<<<grid, 512>>>(p_attn, W_out, b_out, out, Bc * NQ, Dc, Dc);
    }
}